// round 16
// baseline (speedup 1.0000x reference)
#include <cuda_runtime.h>
#include <cuda_bf16.h>
#include <cuda_fp16.h>
#include <math.h>
#include <stdint.h>

// Problem constants
#define BB 2
#define TT 1024
#define DD 1024
#define HH 16
#define DH 64
#define MM 4096
#define VV 50257
#define VP 50304           // VV padded to multiple of 128
#define LL 4
#define BT (BB*TT)          // 2048
#define BTD (BB*TT*DD)      // 2097152

// ---------------- scratch (device globals, no runtime alloc) ----------------
__device__ float g_h[BTD];
__device__ float g_qkv[3*BTD];

// fp16 activation buffers (hi/lo exact splits)
__device__ __half g_ln1h[BTD], g_ln1l[BTD];
__device__ __half g_ath[BTD],  g_atl[BTD];
__device__ __half g_ln2h[BTD], g_ln2l[BTD];
__device__ __half g_mlph[(long)BT*MM], g_mlpl[(long)BT*MM];
__device__ __half g_lnfH[BTD];

// weights (all fp16 single)
__device__ __half g_qkvwH[(long)LL*DD*3*DD];
__device__ __half g_outwH[(long)LL*DD*DD];
__device__ __half g_wiwH[(long)LL*DD*MM];
__device__ __half g_wowH[(long)LL*MM*DD];
__device__ __half g_headwH[(long)DD*VP];

// ---------------- helpers ----------------
__device__ __forceinline__ uint32_t smem_u32(const void* p) {
    return (uint32_t)__cvta_generic_to_shared(p);
}
__device__ __forceinline__ void cp16(void* dst, const void* src) {
    asm volatile("cp.async.cg.shared.global [%0], [%1], 16;\n"
                 :: "r"(smem_u32(dst)), "l"(src));
}
__device__ __forceinline__ void cp_commit() { asm volatile("cp.async.commit_group;\n"); }
__device__ __forceinline__ void cp_wait0()  { asm volatile("cp.async.wait_group 0;\n"); }
__device__ __forceinline__ void cp_wait1()  { asm volatile("cp.async.wait_group 1;\n"); }

__device__ __forceinline__ void ldsm_x4(uint32_t& r0, uint32_t& r1, uint32_t& r2, uint32_t& r3, uint32_t a) {
    asm volatile("ldmatrix.sync.aligned.m8n8.x4.shared.b16 {%0,%1,%2,%3}, [%4];\n"
                 : "=r"(r0), "=r"(r1), "=r"(r2), "=r"(r3) : "r"(a));
}
__device__ __forceinline__ void ldsm_x4_t(uint32_t& r0, uint32_t& r1, uint32_t& r2, uint32_t& r3, uint32_t a) {
    asm volatile("ldmatrix.sync.aligned.m8n8.x4.trans.shared.b16 {%0,%1,%2,%3}, [%4];\n"
                 : "=r"(r0), "=r"(r1), "=r"(r2), "=r"(r3) : "r"(a));
}
__device__ __forceinline__ void mma_fp16(float* c,
        uint32_t a0, uint32_t a1, uint32_t a2, uint32_t a3,
        uint32_t b0, uint32_t b1) {
    asm volatile("mma.sync.aligned.m16n8k16.row.col.f32.f16.f16.f32 "
                 "{%0,%1,%2,%3}, {%4,%5,%6,%7}, {%8,%9}, {%0,%1,%2,%3};\n"
                 : "+f"(c[0]), "+f"(c[1]), "+f"(c[2]), "+f"(c[3])
                 : "r"(a0), "r"(a1), "r"(a2), "r"(a3), "r"(b0), "r"(b1));
}
__device__ __forceinline__ void split_fp16(float f, __half& h, __half& l) {
    h = __float2half(f);
    l = __float2half(f - __half2float(h));
}

// ---------------- weight splitters (fp16 single) ----------------
__global__ void split_w_vec_h(const float* __restrict__ W,
                              __half* __restrict__ Wh,
                              int N) {
    long r = blockIdx.y;
    int c = (blockIdx.x * 256 + threadIdx.x) * 4;
    if (c >= N) return;
    long base = r * N + c;
    float4 v = *reinterpret_cast<const float4*>(W + base);
    *reinterpret_cast<__half2*>(Wh + base)     = __halves2half2(__float2half(v.x), __float2half(v.y));
    *reinterpret_cast<__half2*>(Wh + base + 2) = __halves2half2(__float2half(v.z), __float2half(v.w));
}

__global__ void split_w_pad_h(const float* __restrict__ W,
                              __half* __restrict__ Wh,
                              int N, int Ws) {
    long r = blockIdx.y;
    int c0 = blockIdx.x * 1024;
    #pragma unroll
    for (int p = 0; p < 4; p++) {
        int c = c0 + p * 256 + threadIdx.x;
        if (c < Ws) {
            float f = (c < N) ? W[r * N + c] : 0.f;
            Wh[r * (long)Ws + c] = __float2half(f);
        }
    }
}

// ---------------- embedding (float4) ----------------
__global__ void embed_kernel(const int* __restrict__ x,
                             const float* __restrict__ tok,
                             const float* __restrict__ pos) {
    int i = blockIdx.x * blockDim.x + threadIdx.x;
    if (i >= BTD / 4) return;
    int dv = i & (DD / 4 - 1);
    int bt = i / (DD / 4);
    int t  = bt % TT;
    float4 a = *reinterpret_cast<const float4*>(tok + (long)x[bt] * DD + dv * 4);
    float4 p = *reinterpret_cast<const float4*>(pos + (long)t * DD + dv * 4);
    float4 o = make_float4(a.x + p.x, a.y + p.y, a.z + p.z, a.w + p.w);
    *reinterpret_cast<float4*>(g_h + (long)i * 4) = o;
}

// ---------------- layernorm cores ----------------
__device__ __forceinline__ void ln_compute(const float* xr, int tid, float4& v4,
                                           float& mu, float& rstd, float* red) {
    v4 = *reinterpret_cast<const float4*>(xr + tid * 4);
    float s = v4.x + v4.y + v4.z + v4.w;
    red[tid] = s; __syncthreads();
    for (int st = 128; st > 0; st >>= 1) { if (tid < st) red[tid] += red[tid + st]; __syncthreads(); }
    mu = red[0] * (1.0f / DD);
    __syncthreads();
    float dx = v4.x - mu, dy = v4.y - mu, dz = v4.z - mu, dw = v4.w - mu;
    red[tid] = dx * dx + dy * dy + dz * dz + dw * dw;
    __syncthreads();
    for (int st = 128; st > 0; st >>= 1) { if (tid < st) red[tid] += red[tid + st]; __syncthreads(); }
    rstd = rsqrtf(red[0] * (1.0f / DD) + 1e-5f);
}

__global__ void ln_fp16x2_kernel(const float* __restrict__ x,
                                 const float* __restrict__ g,
                                 const float* __restrict__ b,
                                 __half* __restrict__ yh,
                                 __half* __restrict__ yl) {
    __shared__ float red[256];
    int row = blockIdx.x;
    int tid = threadIdx.x;
    float4 v4; float mu, rstd;
    ln_compute(x + (long)row * DD, tid, v4, mu, rstd, red);

    float4 g4 = *reinterpret_cast<const float4*>(g + tid * 4);
    float4 b4 = *reinterpret_cast<const float4*>(b + tid * 4);
    float y0 = (v4.x - mu) * rstd * g4.x + b4.x;
    float y1 = (v4.y - mu) * rstd * g4.y + b4.y;
    float y2 = (v4.z - mu) * rstd * g4.z + b4.z;
    float y3 = (v4.w - mu) * rstd * g4.w + b4.w;
    __half h0,l0,h1,l1,h2,l2,h3,l3;
    split_fp16(y0,h0,l0); split_fp16(y1,h1,l1); split_fp16(y2,h2,l2); split_fp16(y3,h3,l3);
    long idx = (long)row * DD + tid * 4;
    *reinterpret_cast<__half2*>(yh + idx)     = __halves2half2(h0, h1);
    *reinterpret_cast<__half2*>(yh + idx + 2) = __halves2half2(h2, h3);
    *reinterpret_cast<__half2*>(yl + idx)     = __halves2half2(l0, l1);
    *reinterpret_cast<__half2*>(yl + idx + 2) = __halves2half2(l2, l3);
}

__global__ void ln_fp16_kernel(const float* __restrict__ x,
                               const float* __restrict__ g,
                               const float* __restrict__ b,
                               __half* __restrict__ yh) {
    __shared__ float red[256];
    int row = blockIdx.x;
    int tid = threadIdx.x;
    float4 v4; float mu, rstd;
    ln_compute(x + (long)row * DD, tid, v4, mu, rstd, red);

    float4 g4 = *reinterpret_cast<const float4*>(g + tid * 4);
    float4 b4 = *reinterpret_cast<const float4*>(b + tid * 4);
    float y0 = (v4.x - mu) * rstd * g4.x + b4.x;
    float y1 = (v4.y - mu) * rstd * g4.y + b4.y;
    float y2 = (v4.z - mu) * rstd * g4.z + b4.z;
    float y3 = (v4.w - mu) * rstd * g4.w + b4.w;
    long idx = (long)row * DD + tid * 4;
    *reinterpret_cast<__half2*>(yh + idx)     = __halves2half2(__float2half(y0), __float2half(y1));
    *reinterpret_cast<__half2*>(yh + idx + 2) = __halves2half2(__float2half(y2), __float2half(y3));
}

// ---------------- shared GEMM geometry ----------------
#define AKS 40
#define BNS 136
#define STG_B (32*BNS)

// ---------------- GEMM fp16 2-product, templated BM (64 or 128), 2-stage ----------------
template<int BM>
struct H2Cfg {
    static constexpr int MC = BM / 64;                 // 16-row m-chunks per warp
    static constexpr int STG_A = BM * AKS;
    static constexpr int ELEMS = 2 * STG_A + STG_B;
    static constexpr int SMEM = 2 * ELEMS * 2;
};

template<int BM>
struct H2Stage {
    __half *Ah, *Al, *Bh;
    __device__ __forceinline__ H2Stage(__half* smem, int st) {
        __half* base = smem + st * H2Cfg<BM>::ELEMS;
        Ah = base;
        Al = base + H2Cfg<BM>::STG_A;
        Bh = base + 2 * H2Cfg<BM>::STG_A;
    }
};

template<int BM>
__device__ __forceinline__ void load_h2stage(H2Stage<BM> s, int tid,
        const __half* __restrict__ Agh, const __half* __restrict__ Agl,
        const __half* __restrict__ Wh,
        int m0, int n0, int k0, int K, int Ws) {
    constexpr int PA = BM / 64;     // A passes: 256 threads cover 64 rows x 32 cols
    #pragma unroll
    for (int p = 0; p < PA; p++) {
        int idx = p * 256 + tid;
        int ar = idx >> 2, ac = (idx & 3) * 8;
        long aoff = (long)(m0 + ar) * K + k0 + ac;
        cp16(&s.Ah[ar * AKS + ac], Agh + aoff);
        cp16(&s.Al[ar * AKS + ac], Agl + aoff);
    }
    #pragma unroll
    for (int p = 0; p < 2; p++) {
        int idx = p * 256 + tid;
        int br = idx >> 4, bc = (idx & 15) * 8;
        long boff = (long)(k0 + br) * Ws + n0 + bc;
        cp16(&s.Bh[br * BNS + bc], Wh + boff);
    }
}

// act: 1 = exact GELU. Outputs: Cf (fp32, opt res) and/or Csh/Csl (fp16 split).
template<int BM>
__global__ __launch_bounds__(256)
void gemm_h2(const __half* __restrict__ Agh, const __half* __restrict__ Agl,
             const __half* __restrict__ Wh,
             const float* __restrict__ bias, const float* __restrict__ res,
             float* __restrict__ Cf,
             __half* __restrict__ Csh, __half* __restrict__ Csl,
             int M, int N, int Ws, int K, int act)
{
    constexpr int MC = H2Cfg<BM>::MC;
    extern __shared__ __half hsmem2[];

    int tid  = threadIdx.x;
    int m0   = blockIdx.x * BM;
    int n0   = blockIdx.y * 128;
    int warp = tid >> 5, lane = tid & 31;
    int wm0  = (warp >> 1) * (MC * 16);
    int wn0  = (warp & 1) * 64;
    int gid  = lane >> 2, tig = lane & 3;

    float acc[MC][8][4];
    #pragma unroll
    for (int i = 0; i < MC; i++)
        #pragma unroll
        for (int j = 0; j < 8; j++)
            #pragma unroll
            for (int q = 0; q < 4; q++) acc[i][j][q] = 0.f;

    int nkt = K >> 5;

    load_h2stage<BM>(H2Stage<BM>(hsmem2, 0), tid, Agh, Agl, Wh, m0, n0, 0, K, Ws);
    cp_commit();

    for (int kt = 0; kt < nkt; kt++) {
        if (kt + 1 < nkt) {
            load_h2stage<BM>(H2Stage<BM>(hsmem2, (kt + 1) & 1), tid, Agh, Agl, Wh,
                             m0, n0, (kt + 1) << 5, K, Ws);
            cp_commit();
            cp_wait1();
        } else {
            cp_wait0();
        }
        __syncthreads();

        H2Stage<BM> s(hsmem2, kt & 1);
        #pragma unroll
        for (int kk = 0; kk < 32; kk += 16) {
            uint32_t ah[MC][4], al[MC][4], bh[8][2];
            #pragma unroll
            for (int mc = 0; mc < MC; mc++) {
                int r = wm0 + mc * 16 + (lane & 15);
                int c = kk + ((lane >> 4) << 3);
                ldsm_x4(ah[mc][0], ah[mc][1], ah[mc][2], ah[mc][3], smem_u32(&s.Ah[r * AKS + c]));
                ldsm_x4(al[mc][0], al[mc][1], al[mc][2], al[mc][3], smem_u32(&s.Al[r * AKS + c]));
            }
            #pragma unroll
            for (int pc = 0; pc < 4; pc++) {
                int r = kk + (lane & 15);
                int c = wn0 + pc * 16 + ((lane >> 4) << 3);
                ldsm_x4_t(bh[2*pc][0], bh[2*pc][1], bh[2*pc+1][0], bh[2*pc+1][1], smem_u32(&s.Bh[r * BNS + c]));
            }
            #pragma unroll
            for (int mc = 0; mc < MC; mc++)
                #pragma unroll
                for (int ch = 0; ch < 8; ch++) {
                    mma_fp16(acc[mc][ch], ah[mc][0], ah[mc][1], ah[mc][2], ah[mc][3], bh[ch][0], bh[ch][1]);
                    mma_fp16(acc[mc][ch], al[mc][0], al[mc][1], al[mc][2], al[mc][3], bh[ch][0], bh[ch][1]);
                }
        }
        __syncthreads();
    }

    #pragma unroll
    for (int mc = 0; mc < MC; mc++) {
        #pragma unroll
        for (int ch = 0; ch < 8; ch++) {
            int n = n0 + wn0 + (ch >> 1) * 16 + (ch & 1) * 8 + tig * 2;
            #pragma unroll
            for (int h2 = 0; h2 < 2; h2++) {
                int m = m0 + wm0 + mc * 16 + gid + h2 * 8;
                #pragma unroll
                for (int j = 0; j < 2; j++) {
                    int nn = n + j;
                    if (nn < N) {
                        float v = acc[mc][ch][h2 * 2 + j] + bias[nn];
                        if (act == 1) v = 0.5f * v * (1.0f + erff(v * 0.70710678118654752f));
                        long idx = (long)m * N + nn;
                        if (res) v += res[idx];
                        if (Cf) Cf[idx] = v;
                        if (Csh) {
                            __half hh, ll;
                            split_fp16(v, hh, ll);
                            Csh[idx] = hh; Csl[idx] = ll;
                        }
                    }
                }
            }
        }
    }
}

// ---------------- head GEMM (fp16 single-product, BM=128, 2-stage) ----------------
#define HSTG_A (128*AKS)
#define HSTG_ELEMS (HSTG_A + STG_B)
#define HSMEM_BYTES (2 * HSTG_ELEMS * 2)    // 37888

struct HStage {
    __half *Ah, *Bh;
};
__device__ __forceinline__ HStage hstage_ptrs(__half* smem, int st) {
    __half* base = smem + st * HSTG_ELEMS;
    HStage s;
    s.Ah = base;
    s.Bh = base + HSTG_A;
    return s;
}

__device__ __forceinline__ void load_hstage(HStage s, int tid,
        const __half* __restrict__ Agh, const __half* __restrict__ Wh,
        int m0, int n0, int k0, int K, int Ws) {
    #pragma unroll
    for (int p = 0; p < 2; p++) {
        int idx = p * 256 + tid;
        int ar = idx >> 2, ac = (idx & 3) * 8;
        long aoff = (long)(m0 + ar) * K + k0 + ac;
        cp16(&s.Ah[ar * AKS + ac], Agh + aoff);
        int br = idx >> 4, bc = (idx & 15) * 8;
        long boff = (long)(k0 + br) * Ws + n0 + bc;
        cp16(&s.Bh[br * BNS + bc], Wh + boff);
    }
}

__global__ __launch_bounds__(256)
void gemm_head(const __half* __restrict__ Agh, const __half* __restrict__ Wh,
               const float* __restrict__ bias, float* __restrict__ Cf,
               int M, int N, int Ws, int K)
{
    extern __shared__ __half hsmem[];

    int tid  = threadIdx.x;
    int m0   = blockIdx.x * 128;
    int n0   = blockIdx.y * 128;
    int warp = tid >> 5, lane = tid & 31;
    int wm0  = (warp >> 1) * 32;
    int wn0  = (warp & 1) * 64;
    int gid  = lane >> 2, tig = lane & 3;

    float acc[2][8][4];
    #pragma unroll
    for (int i = 0; i < 2; i++)
        #pragma unroll
        for (int j = 0; j < 8; j++)
            #pragma unroll
            for (int q = 0; q < 4; q++) acc[i][j][q] = 0.f;

    int nkt = K >> 5;

    load_hstage(hstage_ptrs(hsmem, 0), tid, Agh, Wh, m0, n0, 0, K, Ws);
    cp_commit();

    for (int kt = 0; kt < nkt; kt++) {
        if (kt + 1 < nkt) {
            load_hstage(hstage_ptrs(hsmem, (kt + 1) & 1), tid, Agh, Wh,
                        m0, n0, (kt + 1) << 5, K, Ws);
            cp_commit();
            cp_wait1();
        } else {
            cp_wait0();
        }
        __syncthreads();

        HStage s = hstage_ptrs(hsmem, kt & 1);
        #pragma unroll
        for (int kk = 0; kk < 32; kk += 16) {
            uint32_t ah[2][4], bh[8][2];
            #pragma unroll
            for (int mc = 0; mc < 2; mc++) {
                int r = wm0 + mc * 16 + (lane & 15);
                int c = kk + ((lane >> 4) << 3);
                ldsm_x4(ah[mc][0], ah[mc][1], ah[mc][2], ah[mc][3], smem_u32(&s.Ah[r * AKS + c]));
            }
            #pragma unroll
            for (int pc = 0; pc < 4; pc++) {
                int r = kk + (lane & 15);
                int c = wn0 + pc * 16 + ((lane >> 4) << 3);
                ldsm_x4_t(bh[2*pc][0], bh[2*pc][1], bh[2*pc+1][0], bh[2*pc+1][1], smem_u32(&s.Bh[r * BNS + c]));
            }
            #pragma unroll
            for (int mc = 0; mc < 2; mc++)
                #pragma unroll
                for (int ch = 0; ch < 8; ch++)
                    mma_fp16(acc[mc][ch], ah[mc][0], ah[mc][1], ah[mc][2], ah[mc][3], bh[ch][0], bh[ch][1]);
        }
        __syncthreads();
    }

    #pragma unroll
    for (int mc = 0; mc < 2; mc++) {
        #pragma unroll
        for (int ch = 0; ch < 8; ch++) {
            int n = n0 + wn0 + (ch >> 1) * 16 + (ch & 1) * 8 + tig * 2;
            #pragma unroll
            for (int h2 = 0; h2 < 2; h2++) {
                int m = m0 + wm0 + mc * 16 + gid + h2 * 8;
                #pragma unroll
                for (int j = 0; j < 2; j++) {
                    int nn = n + j;
                    if (nn < N) {
                        float v = acc[mc][ch][h2 * 2 + j] + bias[nn];
                        Cf[(long)m * N + nn] = v;
                    }
                }
            }
        }
    }
}

// ---------------- flash attention: 128 queries per block, online softmax ----------------
#define AT_SMEM ((128*65 + 64*65 + 64*65 + 128*65) * 4)

__global__ __launch_bounds__(256)
void attn_flash(const float* __restrict__ qkv,
                __half* __restrict__ oh, __half* __restrict__ ol) {
    extern __shared__ float sm[];
    float* Qs = sm;
    float* Ks = Qs + 128 * 65;
    float* Vs = Ks + 64 * 65;
    float* Ps = Vs + 64 * 65;

    int blk = blockIdx.x;
    int qb = blk & 7;
    int bh = blk >> 3;
    int h  = bh % HH;
    int b  = bh / HH;

    const float* qg = qkv + ((long)(b * TT + qb * 128)) * DD + h * DH;
    const float* kg = qkv + BTD     + ((long)(b * TT)) * DD + h * DH;
    const float* vg = qkv + 2 * BTD + ((long)(b * TT)) * DD + h * DH;

    int tid = threadIdx.x;

    for (int i = tid; i < 128 * 64; i += 256) {
        int r = i >> 6, c = i & 63;
        Qs[r * 65 + c] = qg[(long)r * DD + c];
    }
    __syncthreads();

    int qr = tid >> 1;
    int half = tid & 1;
    int kb = half * 32;

    float m = -1e30f, l = 0.f;
    float O[32];
    #pragma unroll
    for (int d = 0; d < 32; d++) O[d] = 0.f;

    for (int t0 = 0; t0 < TT; t0 += 64) {
        for (int i = tid; i < 64 * 64; i += 256) {
            int r = i >> 6, c = i & 63;
            Ks[r * 65 + c] = kg[(long)(t0 + r) * DD + c];
            Vs[r * 65 + c] = vg[(long)(t0 + r) * DD + c];
        }
        __syncthreads();

        float s[32];
        float cmax = -1e30f;
        #pragma unroll
        for (int kk = 0; kk < 32; kk++) {
            float dot = 0.f;
            #pragma unroll
            for (int d = 0; d < 64; d++)
                dot += Qs[qr * 65 + d] * Ks[(kb + kk) * 65 + d];
            s[kk] = dot * 0.125f;
            cmax = fmaxf(cmax, s[kk]);
        }
        cmax = fmaxf(cmax, __shfl_xor_sync(0xffffffff, cmax, 1));
        float mnew = fmaxf(m, cmax);
        float corr = __expf(m - mnew);

        float lsum = 0.f;
        #pragma unroll
        for (int kk = 0; kk < 32; kk++) {
            float p = __expf(s[kk] - mnew);
            Ps[qr * 65 + kb + kk] = p;
            lsum += p;
        }
        lsum += __shfl_xor_sync(0xffffffff, lsum, 1);
        l = l * corr + lsum;
        #pragma unroll
        for (int d = 0; d < 32; d++) O[d] *= corr;
        m = mnew;
        __syncwarp();

        #pragma unroll 4
        for (int kk = 0; kk < 64; kk++) {
            float p = Ps[qr * 65 + kk];
            #pragma unroll
            for (int d = 0; d < 32; d++)
                O[d] += p * Vs[kk * 65 + kb + d];
        }
        __syncthreads();
    }

    float inv = 1.0f / l;
    long obase = ((long)(b * TT + qb * 128 + qr)) * DD + h * DH + kb;
    #pragma unroll
    for (int d = 0; d < 32; d++) {
        float o = O[d] * inv;
        __half hh, ll;
        split_fp16(o, hh, ll);
        oh[obase + d] = hh;
        ol[obase + d] = ll;
    }
}

// ---------------- host orchestration ----------------
static void run_gemm_h2(const __half* Ah, const __half* Al, const __half* Wh,
                        const float* bias, const float* res, float* Cf,
                        __half* Csh, __half* Csl,
                        int M, int N, int Ws, int K, int act, int bm) {
    if (bm == 64) {
        dim3 grid(M / 64, (N + 127) / 128);
        gemm_h2<64><<<grid, 256, H2Cfg<64>::SMEM>>>(Ah, Al, Wh, bias, res, Cf,
                                                    Csh, Csl, M, N, Ws, K, act);
    } else {
        dim3 grid(M / 128, (N + 127) / 128);
        gemm_h2<128><<<grid, 256, H2Cfg<128>::SMEM>>>(Ah, Al, Wh, bias, res, Cf,
                                                      Csh, Csl, M, N, Ws, K, act);
    }
}

extern "C" void kernel_launch(void* const* d_in, const int* in_sizes, int n_in,
                              void* d_out, int out_size) {
    const int*   x       = (const int*)  d_in[0];
    const float* tok_emb = (const float*)d_in[1];
    const float* pos_emb = (const float*)d_in[2];
    const float* ln1_g   = (const float*)d_in[3];
    const float* ln1_b   = (const float*)d_in[4];
    const float* qkv_w   = (const float*)d_in[5];
    const float* qkv_b   = (const float*)d_in[6];
    const float* out_w   = (const float*)d_in[7];
    const float* out_b   = (const float*)d_in[8];
    const float* ln2_g   = (const float*)d_in[9];
    const float* ln2_b   = (const float*)d_in[10];
    const float* wi_w    = (const float*)d_in[11];
    const float* wi_b    = (const float*)d_in[12];
    const float* wo_w    = (const float*)d_in[13];
    const float* wo_b    = (const float*)d_in[14];
    const float* ln_g    = (const float*)d_in[15];
    const float* ln_b    = (const float*)d_in[16];
    const float* head_w  = (const float*)d_in[17];
    const float* head_b  = (const float*)d_in[18];
    float* logits = (float*)d_out;

    static bool attr_set = false;
    if (!attr_set) {
        cudaFuncSetAttribute(gemm_h2<64>,  cudaFuncAttributeMaxDynamicSharedMemorySize, H2Cfg<64>::SMEM);
        cudaFuncSetAttribute(gemm_h2<128>, cudaFuncAttributeMaxDynamicSharedMemorySize, H2Cfg<128>::SMEM);
        cudaFuncSetAttribute(gemm_head,    cudaFuncAttributeMaxDynamicSharedMemorySize, HSMEM_BYTES);
        cudaFuncSetAttribute(attn_flash,   cudaFuncAttributeMaxDynamicSharedMemorySize, AT_SMEM);
        attr_set = true;
    }

    float *h, *qkv;
    cudaGetSymbolAddress((void**)&h,   g_h);
    cudaGetSymbolAddress((void**)&qkv, g_qkv);
    __half *ln1h, *ln1l, *ath, *atl, *ln2h, *ln2l, *mlph, *mlpl, *lnfH;
    cudaGetSymbolAddress((void**)&ln1h, g_ln1h);
    cudaGetSymbolAddress((void**)&ln1l, g_ln1l);
    cudaGetSymbolAddress((void**)&ath,  g_ath);
    cudaGetSymbolAddress((void**)&atl,  g_atl);
    cudaGetSymbolAddress((void**)&ln2h, g_ln2h);
    cudaGetSymbolAddress((void**)&ln2l, g_ln2l);
    cudaGetSymbolAddress((void**)&mlph, g_mlph);
    cudaGetSymbolAddress((void**)&mlpl, g_mlpl);
    cudaGetSymbolAddress((void**)&lnfH, g_lnfH);
    __half *qkvwH, *outwH, *wiwH, *wowH, *headwH;
    cudaGetSymbolAddress((void**)&qkvwH, g_qkvwH);
    cudaGetSymbolAddress((void**)&outwH, g_outwH);
    cudaGetSymbolAddress((void**)&wiwH,  g_wiwH);
    cudaGetSymbolAddress((void**)&wowH,  g_wowH);
    cudaGetSymbolAddress((void**)&headwH, g_headwH);

    // split all weights (fp16 single)
    {
        dim3 g1(3 * DD / 1024, LL * DD);
        split_w_vec_h<<<g1, 256>>>(qkv_w, qkvwH, 3 * DD);
        dim3 g2(DD / 1024, LL * DD);
        split_w_vec_h<<<g2, 256>>>(out_w, outwH, DD);
        dim3 g3(MM / 1024, LL * DD);
        split_w_vec_h<<<g3, 256>>>(wi_w, wiwH, MM);
        dim3 g4(DD / 1024, LL * MM);
        split_w_vec_h<<<g4, 256>>>(wo_w, wowH, DD);
        dim3 g5((VP + 1023) / 1024, DD);
        split_w_pad_h<<<g5, 256>>>(head_w, headwH, VV, VP);
    }

    embed_kernel<<<(BTD / 4 + 255) / 256, 256>>>(x, tok_emb, pos_emb);

    for (int l = 0; l < LL; l++) {
        // attn block (fp16 2-product); qkv & out use BM=64 (wave-quantization fix)
        ln_fp16x2_kernel<<<BT, 256>>>(h, ln1_g + l * DD, ln1_b + l * DD, ln1h, ln1l);
        run_gemm_h2(ln1h, ln1l, qkvwH + (long)l * DD * 3 * DD,
                    qkv_b + l * 3 * DD, nullptr, qkv, nullptr, nullptr,
                    BT, 3 * DD, 3 * DD, DD, 0, 64);
        attn_flash<<<BB * HH * (TT / 128), 256, AT_SMEM>>>(qkv, ath, atl);
        run_gemm_h2(ath, atl, outwH + (long)l * DD * DD,
                    out_b + l * DD, h, h, nullptr, nullptr,
                    BT, DD, DD, DD, 0, 64);

        // mlp block (fp16 2-product); wi keeps BM=128 (2 clean waves), wo uses BM=64
        ln_fp16x2_kernel<<<BT, 256>>>(h, ln2_g + l * DD, ln2_b + l * DD, ln2h, ln2l);
        run_gemm_h2(ln2h, ln2l, wiwH + (long)l * DD * MM,
                    wi_b + l * MM, nullptr, nullptr, mlph, mlpl,
                    BT, MM, MM, DD, 1, 128);
        run_gemm_h2(mlph, mlpl, wowH + (long)l * MM * DD,
                    wo_b + l * DD, h, h, nullptr, nullptr,
                    BT, DD, DD, MM, 0, 64);
    }

    // final LN (single fp16) + head GEMM (fp16 single-product)
    ln_fp16_kernel<<<BT, 256>>>(h, ln_g, ln_b, lnfH);
    {
        dim3 grid(BT / 128, VP / 128);
        gemm_head<<<grid, 256, HSMEM_BYTES>>>(lnfH, headwH, head_b, logits,
                                              BT, VV, VP, DD);
    }
}

// round 17
// speedup vs baseline: 1.0696x; 1.0696x over previous
#include <cuda_runtime.h>
#include <cuda_bf16.h>
#include <cuda_fp16.h>
#include <math.h>
#include <stdint.h>

// Problem constants
#define BB 2
#define TT 1024
#define DD 1024
#define HH 16
#define DH 64
#define MM 4096
#define VV 50257
#define VP 50304           // VV padded to multiple of 128
#define LL 4
#define BT (BB*TT)          // 2048
#define BTD (BB*TT*DD)      // 2097152

// ---------------- scratch (device globals, no runtime alloc) ----------------
__device__ float g_h[BTD];
__device__ float g_qkv[3*BTD];

// fp16 activation buffers (hi/lo exact splits)
__device__ __half g_ln1h[BTD], g_ln1l[BTD];
__device__ __half g_ath[BTD],  g_atl[BTD];
__device__ __half g_ln2h[BTD], g_ln2l[BTD];
__device__ __half g_mlph[(long)BT*MM], g_mlpl[(long)BT*MM];
__device__ __half g_lnfH[BTD];

// weights (all fp16 single)
__device__ __half g_qkvwH[(long)LL*DD*3*DD];
__device__ __half g_outwH[(long)LL*DD*DD];
__device__ __half g_wiwH[(long)LL*DD*MM];
__device__ __half g_wowH[(long)LL*MM*DD];
__device__ __half g_headwH[(long)DD*VP];

// ---------------- helpers ----------------
__device__ __forceinline__ uint32_t smem_u32(const void* p) {
    return (uint32_t)__cvta_generic_to_shared(p);
}
__device__ __forceinline__ void cp16(void* dst, const void* src) {
    asm volatile("cp.async.cg.shared.global [%0], [%1], 16;\n"
                 :: "r"(smem_u32(dst)), "l"(src));
}
__device__ __forceinline__ void cp_commit() { asm volatile("cp.async.commit_group;\n"); }
__device__ __forceinline__ void cp_wait0()  { asm volatile("cp.async.wait_group 0;\n"); }
__device__ __forceinline__ void cp_wait1()  { asm volatile("cp.async.wait_group 1;\n"); }

__device__ __forceinline__ void ldsm_x4(uint32_t& r0, uint32_t& r1, uint32_t& r2, uint32_t& r3, uint32_t a) {
    asm volatile("ldmatrix.sync.aligned.m8n8.x4.shared.b16 {%0,%1,%2,%3}, [%4];\n"
                 : "=r"(r0), "=r"(r1), "=r"(r2), "=r"(r3) : "r"(a));
}
__device__ __forceinline__ void ldsm_x4_t(uint32_t& r0, uint32_t& r1, uint32_t& r2, uint32_t& r3, uint32_t a) {
    asm volatile("ldmatrix.sync.aligned.m8n8.x4.trans.shared.b16 {%0,%1,%2,%3}, [%4];\n"
                 : "=r"(r0), "=r"(r1), "=r"(r2), "=r"(r3) : "r"(a));
}
__device__ __forceinline__ void mma_fp16(float* c,
        uint32_t a0, uint32_t a1, uint32_t a2, uint32_t a3,
        uint32_t b0, uint32_t b1) {
    asm volatile("mma.sync.aligned.m16n8k16.row.col.f32.f16.f16.f32 "
                 "{%0,%1,%2,%3}, {%4,%5,%6,%7}, {%8,%9}, {%0,%1,%2,%3};\n"
                 : "+f"(c[0]), "+f"(c[1]), "+f"(c[2]), "+f"(c[3])
                 : "r"(a0), "r"(a1), "r"(a2), "r"(a3), "r"(b0), "r"(b1));
}
__device__ __forceinline__ void split_fp16(float f, __half& h, __half& l) {
    h = __float2half(f);
    l = __float2half(f - __half2float(h));
}

// ---------------- weight splitters (fp16 single) ----------------
__global__ void split_w_vec_h(const float* __restrict__ W,
                              __half* __restrict__ Wh,
                              int N) {
    long r = blockIdx.y;
    int c = (blockIdx.x * 256 + threadIdx.x) * 4;
    if (c >= N) return;
    long base = r * N + c;
    float4 v = *reinterpret_cast<const float4*>(W + base);
    *reinterpret_cast<__half2*>(Wh + base)     = __halves2half2(__float2half(v.x), __float2half(v.y));
    *reinterpret_cast<__half2*>(Wh + base + 2) = __halves2half2(__float2half(v.z), __float2half(v.w));
}

__global__ void split_w_pad_h(const float* __restrict__ W,
                              __half* __restrict__ Wh,
                              int N, int Ws) {
    long r = blockIdx.y;
    int c0 = blockIdx.x * 1024;
    #pragma unroll
    for (int p = 0; p < 4; p++) {
        int c = c0 + p * 256 + threadIdx.x;
        if (c < Ws) {
            float f = (c < N) ? W[r * N + c] : 0.f;
            Wh[r * (long)Ws + c] = __float2half(f);
        }
    }
}

// ---------------- embedding (float4) ----------------
__global__ void embed_kernel(const int* __restrict__ x,
                             const float* __restrict__ tok,
                             const float* __restrict__ pos) {
    int i = blockIdx.x * blockDim.x + threadIdx.x;
    if (i >= BTD / 4) return;
    int dv = i & (DD / 4 - 1);
    int bt = i / (DD / 4);
    int t  = bt % TT;
    float4 a = *reinterpret_cast<const float4*>(tok + (long)x[bt] * DD + dv * 4);
    float4 p = *reinterpret_cast<const float4*>(pos + (long)t * DD + dv * 4);
    float4 o = make_float4(a.x + p.x, a.y + p.y, a.z + p.z, a.w + p.w);
    *reinterpret_cast<float4*>(g_h + (long)i * 4) = o;
}

// ---------------- layernorm cores ----------------
__device__ __forceinline__ void ln_compute(const float* xr, int tid, float4& v4,
                                           float& mu, float& rstd, float* red) {
    v4 = *reinterpret_cast<const float4*>(xr + tid * 4);
    float s = v4.x + v4.y + v4.z + v4.w;
    red[tid] = s; __syncthreads();
    for (int st = 128; st > 0; st >>= 1) { if (tid < st) red[tid] += red[tid + st]; __syncthreads(); }
    mu = red[0] * (1.0f / DD);
    __syncthreads();
    float dx = v4.x - mu, dy = v4.y - mu, dz = v4.z - mu, dw = v4.w - mu;
    red[tid] = dx * dx + dy * dy + dz * dz + dw * dw;
    __syncthreads();
    for (int st = 128; st > 0; st >>= 1) { if (tid < st) red[tid] += red[tid + st]; __syncthreads(); }
    rstd = rsqrtf(red[0] * (1.0f / DD) + 1e-5f);
}

__global__ void ln_fp16x2_kernel(const float* __restrict__ x,
                                 const float* __restrict__ g,
                                 const float* __restrict__ b,
                                 __half* __restrict__ yh,
                                 __half* __restrict__ yl) {
    __shared__ float red[256];
    int row = blockIdx.x;
    int tid = threadIdx.x;
    float4 v4; float mu, rstd;
    ln_compute(x + (long)row * DD, tid, v4, mu, rstd, red);

    float4 g4 = *reinterpret_cast<const float4*>(g + tid * 4);
    float4 b4 = *reinterpret_cast<const float4*>(b + tid * 4);
    float y0 = (v4.x - mu) * rstd * g4.x + b4.x;
    float y1 = (v4.y - mu) * rstd * g4.y + b4.y;
    float y2 = (v4.z - mu) * rstd * g4.z + b4.z;
    float y3 = (v4.w - mu) * rstd * g4.w + b4.w;
    __half h0,l0,h1,l1,h2,l2,h3,l3;
    split_fp16(y0,h0,l0); split_fp16(y1,h1,l1); split_fp16(y2,h2,l2); split_fp16(y3,h3,l3);
    long idx = (long)row * DD + tid * 4;
    *reinterpret_cast<__half2*>(yh + idx)     = __halves2half2(h0, h1);
    *reinterpret_cast<__half2*>(yh + idx + 2) = __halves2half2(h2, h3);
    *reinterpret_cast<__half2*>(yl + idx)     = __halves2half2(l0, l1);
    *reinterpret_cast<__half2*>(yl + idx + 2) = __halves2half2(l2, l3);
}

__global__ void ln_fp16_kernel(const float* __restrict__ x,
                               const float* __restrict__ g,
                               const float* __restrict__ b,
                               __half* __restrict__ yh) {
    __shared__ float red[256];
    int row = blockIdx.x;
    int tid = threadIdx.x;
    float4 v4; float mu, rstd;
    ln_compute(x + (long)row * DD, tid, v4, mu, rstd, red);

    float4 g4 = *reinterpret_cast<const float4*>(g + tid * 4);
    float4 b4 = *reinterpret_cast<const float4*>(b + tid * 4);
    float y0 = (v4.x - mu) * rstd * g4.x + b4.x;
    float y1 = (v4.y - mu) * rstd * g4.y + b4.y;
    float y2 = (v4.z - mu) * rstd * g4.z + b4.z;
    float y3 = (v4.w - mu) * rstd * g4.w + b4.w;
    long idx = (long)row * DD + tid * 4;
    *reinterpret_cast<__half2*>(yh + idx)     = __halves2half2(__float2half(y0), __float2half(y1));
    *reinterpret_cast<__half2*>(yh + idx + 2) = __halves2half2(__float2half(y2), __float2half(y3));
}

// ---------------- shared GEMM geometry ----------------
#define AKS 40
#define BNS 136
#define STG_A (128*AKS)
#define STG_B (32*BNS)

// ---------------- GEMM fp16 2-product (R14-proven: BM=128, 2-stage) ----------------
#define H2STG_ELEMS (2*STG_A + STG_B)       // 14592 halves
#define H2SMEM_BYTES (2 * H2STG_ELEMS * 2)  // 58368

struct H2Stage {
    __half *Ah, *Al, *Bh;
};
__device__ __forceinline__ H2Stage h2stage_ptrs(__half* smem, int st) {
    __half* base = smem + st * H2STG_ELEMS;
    H2Stage s;
    s.Ah = base;
    s.Al = base + STG_A;
    s.Bh = base + 2 * STG_A;
    return s;
}

__device__ __forceinline__ void load_h2stage(H2Stage s, int tid,
        const __half* __restrict__ Agh, const __half* __restrict__ Agl,
        const __half* __restrict__ Wh,
        int m0, int n0, int k0, int K, int Ws) {
    #pragma unroll
    for (int p = 0; p < 2; p++) {
        int idx = p * 256 + tid;
        int ar = idx >> 2, ac = (idx & 3) * 8;
        long aoff = (long)(m0 + ar) * K + k0 + ac;
        cp16(&s.Ah[ar * AKS + ac], Agh + aoff);
        cp16(&s.Al[ar * AKS + ac], Agl + aoff);
        int br = idx >> 4, bc = (idx & 15) * 8;
        long boff = (long)(k0 + br) * Ws + n0 + bc;
        cp16(&s.Bh[br * BNS + bc], Wh + boff);
    }
}

__global__ __launch_bounds__(256)
void gemm_h2(const __half* __restrict__ Agh, const __half* __restrict__ Agl,
             const __half* __restrict__ Wh,
             const float* __restrict__ bias, const float* __restrict__ res,
             float* __restrict__ Cf,
             __half* __restrict__ Csh, __half* __restrict__ Csl,
             int M, int N, int Ws, int K, int act)
{
    extern __shared__ __half hsmem2[];

    int tid  = threadIdx.x;
    int m0   = blockIdx.x * 128;
    int n0   = blockIdx.y * 128;
    int warp = tid >> 5, lane = tid & 31;
    int wm0  = (warp >> 1) * 32;
    int wn0  = (warp & 1) * 64;
    int gid  = lane >> 2, tig = lane & 3;

    float acc[2][8][4];
    #pragma unroll
    for (int i = 0; i < 2; i++)
        #pragma unroll
        for (int j = 0; j < 8; j++)
            #pragma unroll
            for (int q = 0; q < 4; q++) acc[i][j][q] = 0.f;

    int nkt = K >> 5;

    load_h2stage(h2stage_ptrs(hsmem2, 0), tid, Agh, Agl, Wh, m0, n0, 0, K, Ws);
    cp_commit();

    for (int kt = 0; kt < nkt; kt++) {
        if (kt + 1 < nkt) {
            load_h2stage(h2stage_ptrs(hsmem2, (kt + 1) & 1), tid, Agh, Agl, Wh,
                         m0, n0, (kt + 1) << 5, K, Ws);
            cp_commit();
            cp_wait1();
        } else {
            cp_wait0();
        }
        __syncthreads();

        H2Stage s = h2stage_ptrs(hsmem2, kt & 1);
        #pragma unroll
        for (int kk = 0; kk < 32; kk += 16) {
            uint32_t ah[2][4], al[2][4], bh[8][2];
            #pragma unroll
            for (int mc = 0; mc < 2; mc++) {
                int r = wm0 + mc * 16 + (lane & 15);
                int c = kk + ((lane >> 4) << 3);
                ldsm_x4(ah[mc][0], ah[mc][1], ah[mc][2], ah[mc][3], smem_u32(&s.Ah[r * AKS + c]));
                ldsm_x4(al[mc][0], al[mc][1], al[mc][2], al[mc][3], smem_u32(&s.Al[r * AKS + c]));
            }
            #pragma unroll
            for (int pc = 0; pc < 4; pc++) {
                int r = kk + (lane & 15);
                int c = wn0 + pc * 16 + ((lane >> 4) << 3);
                ldsm_x4_t(bh[2*pc][0], bh[2*pc][1], bh[2*pc+1][0], bh[2*pc+1][1], smem_u32(&s.Bh[r * BNS + c]));
            }
            #pragma unroll
            for (int mc = 0; mc < 2; mc++)
                #pragma unroll
                for (int ch = 0; ch < 8; ch++) {
                    mma_fp16(acc[mc][ch], ah[mc][0], ah[mc][1], ah[mc][2], ah[mc][3], bh[ch][0], bh[ch][1]);
                    mma_fp16(acc[mc][ch], al[mc][0], al[mc][1], al[mc][2], al[mc][3], bh[ch][0], bh[ch][1]);
                }
        }
        __syncthreads();
    }

    #pragma unroll
    for (int mc = 0; mc < 2; mc++) {
        #pragma unroll
        for (int ch = 0; ch < 8; ch++) {
            int n = n0 + wn0 + (ch >> 1) * 16 + (ch & 1) * 8 + tig * 2;
            #pragma unroll
            for (int h2 = 0; h2 < 2; h2++) {
                int m = m0 + wm0 + mc * 16 + gid + h2 * 8;
                #pragma unroll
                for (int j = 0; j < 2; j++) {
                    int nn = n + j;
                    if (nn < N) {
                        float v = acc[mc][ch][h2 * 2 + j] + bias[nn];
                        if (act == 1) v = 0.5f * v * (1.0f + erff(v * 0.70710678118654752f));
                        long idx = (long)m * N + nn;
                        if (res) v += res[idx];
                        if (Cf) Cf[idx] = v;
                        if (Csh) {
                            __half hh, ll;
                            split_fp16(v, hh, ll);
                            Csh[idx] = hh; Csl[idx] = ll;
                        }
                    }
                }
            }
        }
    }
}

// ---------------- head GEMM (fp16 single-product, 2-stage) ----------------
#define HSTG_ELEMS (STG_A + STG_B)
#define HSMEM_BYTES (2 * HSTG_ELEMS * 2)    // 37888

struct HStage {
    __half *Ah, *Bh;
};
__device__ __forceinline__ HStage hstage_ptrs(__half* smem, int st) {
    __half* base = smem + st * HSTG_ELEMS;
    HStage s;
    s.Ah = base;
    s.Bh = base + STG_A;
    return s;
}

__device__ __forceinline__ void load_hstage(HStage s, int tid,
        const __half* __restrict__ Agh, const __half* __restrict__ Wh,
        int m0, int n0, int k0, int K, int Ws) {
    #pragma unroll
    for (int p = 0; p < 2; p++) {
        int idx = p * 256 + tid;
        int ar = idx >> 2, ac = (idx & 3) * 8;
        long aoff = (long)(m0 + ar) * K + k0 + ac;
        cp16(&s.Ah[ar * AKS + ac], Agh + aoff);
        int br = idx >> 4, bc = (idx & 15) * 8;
        long boff = (long)(k0 + br) * Ws + n0 + bc;
        cp16(&s.Bh[br * BNS + bc], Wh + boff);
    }
}

__global__ __launch_bounds__(256)
void gemm_head(const __half* __restrict__ Agh, const __half* __restrict__ Wh,
               const float* __restrict__ bias, float* __restrict__ Cf,
               int M, int N, int Ws, int K)
{
    extern __shared__ __half hsmem[];

    int tid  = threadIdx.x;
    int m0   = blockIdx.x * 128;
    int n0   = blockIdx.y * 128;
    int warp = tid >> 5, lane = tid & 31;
    int wm0  = (warp >> 1) * 32;
    int wn0  = (warp & 1) * 64;
    int gid  = lane >> 2, tig = lane & 3;

    float acc[2][8][4];
    #pragma unroll
    for (int i = 0; i < 2; i++)
        #pragma unroll
        for (int j = 0; j < 8; j++)
            #pragma unroll
            for (int q = 0; q < 4; q++) acc[i][j][q] = 0.f;

    int nkt = K >> 5;

    load_hstage(hstage_ptrs(hsmem, 0), tid, Agh, Wh, m0, n0, 0, K, Ws);
    cp_commit();

    for (int kt = 0; kt < nkt; kt++) {
        if (kt + 1 < nkt) {
            load_hstage(hstage_ptrs(hsmem, (kt + 1) & 1), tid, Agh, Wh,
                        m0, n0, (kt + 1) << 5, K, Ws);
            cp_commit();
            cp_wait1();
        } else {
            cp_wait0();
        }
        __syncthreads();

        HStage s = hstage_ptrs(hsmem, kt & 1);
        #pragma unroll
        for (int kk = 0; kk < 32; kk += 16) {
            uint32_t ah[2][4], bh[8][2];
            #pragma unroll
            for (int mc = 0; mc < 2; mc++) {
                int r = wm0 + mc * 16 + (lane & 15);
                int c = kk + ((lane >> 4) << 3);
                ldsm_x4(ah[mc][0], ah[mc][1], ah[mc][2], ah[mc][3], smem_u32(&s.Ah[r * AKS + c]));
            }
            #pragma unroll
            for (int pc = 0; pc < 4; pc++) {
                int r = kk + (lane & 15);
                int c = wn0 + pc * 16 + ((lane >> 4) << 3);
                ldsm_x4_t(bh[2*pc][0], bh[2*pc][1], bh[2*pc+1][0], bh[2*pc+1][1], smem_u32(&s.Bh[r * BNS + c]));
            }
            #pragma unroll
            for (int mc = 0; mc < 2; mc++)
                #pragma unroll
                for (int ch = 0; ch < 8; ch++)
                    mma_fp16(acc[mc][ch], ah[mc][0], ah[mc][1], ah[mc][2], ah[mc][3], bh[ch][0], bh[ch][1]);
        }
        __syncthreads();
    }

    #pragma unroll
    for (int mc = 0; mc < 2; mc++) {
        #pragma unroll
        for (int ch = 0; ch < 8; ch++) {
            int n = n0 + wn0 + (ch >> 1) * 16 + (ch & 1) * 8 + tig * 2;
            #pragma unroll
            for (int h2 = 0; h2 < 2; h2++) {
                int m = m0 + wm0 + mc * 16 + gid + h2 * 8;
                #pragma unroll
                for (int j = 0; j < 2; j++) {
                    int nn = n + j;
                    if (nn < N) {
                        float v = acc[mc][ch][h2 * 2 + j] + bias[nn];
                        Cf[(long)m * N + nn] = v;
                    }
                }
            }
        }
    }
}

// ---------------- flash attention: float4 smem reads, stride 68 ----------------
#define ATS 68
#define AT_SMEM ((128*ATS + 64*ATS + 64*ATS + 128*ATS) * 4)   // 104448

__global__ __launch_bounds__(256)
void attn_flash(const float* __restrict__ qkv,
                __half* __restrict__ oh, __half* __restrict__ ol) {
    extern __shared__ float sm[];
    float* Qs = sm;                    // 128 x ATS
    float* Ks = Qs + 128 * ATS;        // 64 x ATS
    float* Vs = Ks + 64 * ATS;         // 64 x ATS
    float* Ps = Vs + 64 * ATS;         // 128 x ATS

    int blk = blockIdx.x;
    int qb = blk & 7;
    int bh = blk >> 3;
    int h  = bh % HH;
    int b  = bh / HH;

    const float* qg = qkv + ((long)(b * TT + qb * 128)) * DD + h * DH;
    const float* kg = qkv + BTD     + ((long)(b * TT)) * DD + h * DH;
    const float* vg = qkv + 2 * BTD + ((long)(b * TT)) * DD + h * DH;

    int tid = threadIdx.x;

    for (int i = tid; i < 128 * 64; i += 256) {
        int r = i >> 6, c = i & 63;
        Qs[r * ATS + c] = qg[(long)r * DD + c];
    }
    __syncthreads();

    int qr = tid >> 1;
    int half = tid & 1;
    int kb = half * 32;

    float m = -1e30f, l = 0.f;
    float O[32];
    #pragma unroll
    for (int d = 0; d < 32; d++) O[d] = 0.f;

    for (int t0 = 0; t0 < TT; t0 += 64) {
        for (int i = tid; i < 64 * 64; i += 256) {
            int r = i >> 6, c = i & 63;
            Ks[r * ATS + c] = kg[(long)(t0 + r) * DD + c];
            Vs[r * ATS + c] = vg[(long)(t0 + r) * DD + c];
        }
        __syncthreads();

        // scores: d4 outer (Q float4 register-cached), kk inner
        float s[32];
        #pragma unroll
        for (int kk = 0; kk < 32; kk++) s[kk] = 0.f;
        #pragma unroll 2
        for (int d4 = 0; d4 < 16; d4++) {
            float4 q4 = *reinterpret_cast<const float4*>(&Qs[qr * ATS + d4 * 4]);
            #pragma unroll
            for (int kk = 0; kk < 32; kk++) {
                float4 k4 = *reinterpret_cast<const float4*>(&Ks[(kb + kk) * ATS + d4 * 4]);
                s[kk] += q4.x * k4.x + q4.y * k4.y + q4.z * k4.z + q4.w * k4.w;
            }
        }
        float cmax = -1e30f;
        #pragma unroll
        for (int kk = 0; kk < 32; kk++) {
            s[kk] *= 0.125f;
            cmax = fmaxf(cmax, s[kk]);
        }
        cmax = fmaxf(cmax, __shfl_xor_sync(0xffffffff, cmax, 1));
        float mnew = fmaxf(m, cmax);
        float corr = __expf(m - mnew);

        float lsum = 0.f;
        #pragma unroll
        for (int kk = 0; kk < 32; kk++) {
            float p = __expf(s[kk] - mnew);
            Ps[qr * ATS + kb + kk] = p;
            lsum += p;
        }
        lsum += __shfl_xor_sync(0xffffffff, lsum, 1);
        l = l * corr + lsum;
        #pragma unroll
        for (int d = 0; d < 32; d++) O[d] *= corr;
        m = mnew;
        __syncwarp();

        // O += P @ V  (V float4 reads)
        #pragma unroll 4
        for (int kk = 0; kk < 64; kk++) {
            float p = Ps[qr * ATS + kk];
            #pragma unroll
            for (int d4 = 0; d4 < 8; d4++) {
                float4 v4 = *reinterpret_cast<const float4*>(&Vs[kk * ATS + kb + d4 * 4]);
                O[d4 * 4 + 0] += p * v4.x;
                O[d4 * 4 + 1] += p * v4.y;
                O[d4 * 4 + 2] += p * v4.z;
                O[d4 * 4 + 3] += p * v4.w;
            }
        }
        __syncthreads();
    }

    float inv = 1.0f / l;
    long obase = ((long)(b * TT + qb * 128 + qr)) * DD + h * DH + kb;
    #pragma unroll
    for (int d = 0; d < 32; d++) {
        float o = O[d] * inv;
        __half hh, ll;
        split_fp16(o, hh, ll);
        oh[obase + d] = hh;
        ol[obase + d] = ll;
    }
}

// ---------------- host orchestration ----------------
static void run_gemm_h2(const __half* Ah, const __half* Al, const __half* Wh,
                        const float* bias, const float* res, float* Cf,
                        __half* Csh, __half* Csl,
                        int M, int N, int Ws, int K, int act) {
    dim3 grid(M / 128, (N + 127) / 128);
    gemm_h2<<<grid, 256, H2SMEM_BYTES>>>(Ah, Al, Wh, bias, res, Cf, Csh, Csl,
                                         M, N, Ws, K, act);
}

extern "C" void kernel_launch(void* const* d_in, const int* in_sizes, int n_in,
                              void* d_out, int out_size) {
    const int*   x       = (const int*)  d_in[0];
    const float* tok_emb = (const float*)d_in[1];
    const float* pos_emb = (const float*)d_in[2];
    const float* ln1_g   = (const float*)d_in[3];
    const float* ln1_b   = (const float*)d_in[4];
    const float* qkv_w   = (const float*)d_in[5];
    const float* qkv_b   = (const float*)d_in[6];
    const float* out_w   = (const float*)d_in[7];
    const float* out_b   = (const float*)d_in[8];
    const float* ln2_g   = (const float*)d_in[9];
    const float* ln2_b   = (const float*)d_in[10];
    const float* wi_w    = (const float*)d_in[11];
    const float* wi_b    = (const float*)d_in[12];
    const float* wo_w    = (const float*)d_in[13];
    const float* wo_b    = (const float*)d_in[14];
    const float* ln_g    = (const float*)d_in[15];
    const float* ln_b    = (const float*)d_in[16];
    const float* head_w  = (const float*)d_in[17];
    const float* head_b  = (const float*)d_in[18];
    float* logits = (float*)d_out;

    static bool attr_set = false;
    if (!attr_set) {
        cudaFuncSetAttribute(gemm_h2,    cudaFuncAttributeMaxDynamicSharedMemorySize, H2SMEM_BYTES);
        cudaFuncSetAttribute(gemm_head,  cudaFuncAttributeMaxDynamicSharedMemorySize, HSMEM_BYTES);
        cudaFuncSetAttribute(attn_flash, cudaFuncAttributeMaxDynamicSharedMemorySize, AT_SMEM);
        attr_set = true;
    }

    float *h, *qkv;
    cudaGetSymbolAddress((void**)&h,   g_h);
    cudaGetSymbolAddress((void**)&qkv, g_qkv);
    __half *ln1h, *ln1l, *ath, *atl, *ln2h, *ln2l, *mlph, *mlpl, *lnfH;
    cudaGetSymbolAddress((void**)&ln1h, g_ln1h);
    cudaGetSymbolAddress((void**)&ln1l, g_ln1l);
    cudaGetSymbolAddress((void**)&ath,  g_ath);
    cudaGetSymbolAddress((void**)&atl,  g_atl);
    cudaGetSymbolAddress((void**)&ln2h, g_ln2h);
    cudaGetSymbolAddress((void**)&ln2l, g_ln2l);
    cudaGetSymbolAddress((void**)&mlph, g_mlph);
    cudaGetSymbolAddress((void**)&mlpl, g_mlpl);
    cudaGetSymbolAddress((void**)&lnfH, g_lnfH);
    __half *qkvwH, *outwH, *wiwH, *wowH, *headwH;
    cudaGetSymbolAddress((void**)&qkvwH, g_qkvwH);
    cudaGetSymbolAddress((void**)&outwH, g_outwH);
    cudaGetSymbolAddress((void**)&wiwH,  g_wiwH);
    cudaGetSymbolAddress((void**)&wowH,  g_wowH);
    cudaGetSymbolAddress((void**)&headwH, g_headwH);

    // split all weights (fp16 single)
    {
        dim3 g1(3 * DD / 1024, LL * DD);
        split_w_vec_h<<<g1, 256>>>(qkv_w, qkvwH, 3 * DD);
        dim3 g2(DD / 1024, LL * DD);
        split_w_vec_h<<<g2, 256>>>(out_w, outwH, DD);
        dim3 g3(MM / 1024, LL * DD);
        split_w_vec_h<<<g3, 256>>>(wi_w, wiwH, MM);
        dim3 g4(DD / 1024, LL * MM);
        split_w_vec_h<<<g4, 256>>>(wo_w, wowH, DD);
        dim3 g5((VP + 1023) / 1024, DD);
        split_w_pad_h<<<g5, 256>>>(head_w, headwH, VV, VP);
    }

    embed_kernel<<<(BTD / 4 + 255) / 256, 256>>>(x, tok_emb, pos_emb);

    for (int l = 0; l < LL; l++) {
        // attn block (fp16 2-product)
        ln_fp16x2_kernel<<<BT, 256>>>(h, ln1_g + l * DD, ln1_b + l * DD, ln1h, ln1l);
        run_gemm_h2(ln1h, ln1l, qkvwH + (long)l * DD * 3 * DD,
                    qkv_b + l * 3 * DD, nullptr, qkv, nullptr, nullptr,
                    BT, 3 * DD, 3 * DD, DD, 0);
        attn_flash<<<BB * HH * (TT / 128), 256, AT_SMEM>>>(qkv, ath, atl);
        run_gemm_h2(ath, atl, outwH + (long)l * DD * DD,
                    out_b + l * DD, h, h, nullptr, nullptr,
                    BT, DD, DD, DD, 0);

        // mlp block (fp16 2-product)
        ln_fp16x2_kernel<<<BT, 256>>>(h, ln2_g + l * DD, ln2_b + l * DD, ln2h, ln2l);
        run_gemm_h2(ln2h, ln2l, wiwH + (long)l * DD * MM,
                    wi_b + l * MM, nullptr, nullptr, mlph, mlpl,
                    BT, MM, MM, DD, 1);
        run_gemm_h2(mlph, mlpl, wowH + (long)l * MM * DD,
                    wo_b + l * DD, h, h, nullptr, nullptr,
                    BT, DD, DD, MM, 0);
    }

    // final LN (single fp16) + head GEMM (fp16 single-product)
    ln_fp16_kernel<<<BT, 256>>>(h, ln_g, ln_b, lnfH);
    {
        dim3 grid(BT / 128, VP / 128);
        gemm_head<<<grid, 256, HSMEM_BYTES>>>(lnfH, headwH, head_b, logits,
                                              BT, VV, VP, DD);
    }
}